// round 9
// baseline (speedup 1.0000x reference)
#include <cuda_runtime.h>

// Problem constants (fixed shapes from reference_code)
#define E_    3
#define QE_   60000
#define P_    40
#define H_    20
#define NIMG_ 1800
#define Q_    (E_ * QE_)        // 180000 atoms
#define NNZ_  14400000
#define AB    256               // atoms per hist block
#define NB    704               // ceil(Q_/AB)
#define NBD   352               // k_mlp CTAs (2 hist blocks each)

// Scratch (static device globals — sanctioned)
__device__ float g_dE[(size_t)Q_ * P_];        // NEGATED dE/dFP, sorted order, 28.8 MB
__device__ int   g_hist[(size_t)NIMG_ * NB];
__device__ int   g_key_total[NIMG_];
__device__ int   g_key_base[NIMG_];

__device__ __forceinline__ float tanh_fast(float x) {
    float y;
    asm("tanh.approx.f32 %0, %1;" : "=f"(y) : "f"(x));
    return y;
}

// ---------------------------------------------------------------------------
// Histogram of image_idx, fused with zeroing of the output buffer.
// ---------------------------------------------------------------------------
__global__ void k_hist(const int* __restrict__ idx,
                       float* __restrict__ out, int out_n) {
    __shared__ int h[NIMG_];
    for (int k = threadIdx.x; k < NIMG_; k += blockDim.x) h[k] = 0;

    for (int i = blockIdx.x * AB + threadIdx.x; i < out_n; i += NB * AB)
        out[i] = 0.0f;
    __syncthreads();

    int a = blockIdx.x * AB + threadIdx.x;
    if (a < Q_) atomicAdd(&h[idx[a]], 1);
    __syncthreads();
    for (int k = threadIdx.x; k < NIMG_; k += blockDim.x)
        g_hist[(size_t)k * NB + blockIdx.x] = h[k];
}

// ---------------------------------------------------------------------------
// Per-key exclusive scan over blocks: warp-shuffle 2-level scan.
// ---------------------------------------------------------------------------
__global__ void k_scan_blocks() {
    __shared__ int wsum[22];
    int k = blockIdx.x, t = threadIdx.x;
    int lane = t & 31, w = t >> 5;
    int v = g_hist[(size_t)k * NB + t];
    int s = v;
    #pragma unroll
    for (int o = 1; o < 32; o <<= 1) {
        int x = __shfl_up_sync(0xFFFFFFFFu, s, o);
        if (lane >= o) s += x;
    }
    if (lane == 31) wsum[w] = s;
    __syncthreads();
    if (w == 0) {
        int ws = (lane < 22) ? wsum[lane] : 0;
        #pragma unroll
        for (int o = 1; o < 32; o <<= 1) {
            int x = __shfl_up_sync(0xFFFFFFFFu, ws, o);
            if (lane >= o) ws += x;
        }
        if (lane < 22) wsum[lane] = ws;
    }
    __syncthreads();
    int incl = ((w > 0) ? wsum[w - 1] : 0) + s;
    g_hist[(size_t)k * NB + t] = incl - v;   // exclusive
    if (t == NB - 1) g_key_total[k] = incl;
}

// ---------------------------------------------------------------------------
// Exclusive scan over 1800 key totals (2 elems/thread, shuffle scan).
// ---------------------------------------------------------------------------
__global__ void k_scan_keys() {
    __shared__ int wsum[32];
    int t = threadIdx.x, lane = t & 31, w = t >> 5;
    int i0 = 2 * t, i1 = 2 * t + 1;
    int v0 = (i0 < NIMG_) ? g_key_total[i0] : 0;
    int v1 = (i1 < NIMG_) ? g_key_total[i1] : 0;
    int p = v0 + v1, s = p;
    #pragma unroll
    for (int o = 1; o < 32; o <<= 1) {
        int x = __shfl_up_sync(0xFFFFFFFFu, s, o);
        if (lane >= o) s += x;
    }
    if (lane == 31) wsum[w] = s;
    __syncthreads();
    if (w == 0) {
        int ws = wsum[lane];
        #pragma unroll
        for (int o = 1; o < 32; o <<= 1) {
            int x = __shfl_up_sync(0xFFFFFFFFu, ws, o);
            if (lane >= o) ws += x;
        }
        wsum[lane] = ws;
    }
    __syncthreads();
    int excl = ((w > 0) ? wsum[w - 1] : 0) + s - p;
    if (i0 < NIMG_) g_key_base[i0] = excl;
    if (i1 < NIMG_) g_key_base[i1] = excl + v0;
}

// ---------------------------------------------------------------------------
// Single-atom MLP (slow path for boundary warps) — identical math to R8.
// ---------------------------------------------------------------------------
__device__ __forceinline__ void mlp_one(
    const float* __restrict__ fps, int a, int e, int pos, int key,
    const float* w1base, const float* w1tbase, const float* w2base,
    const float* w2tbase, const float* sB1, const float* sB2,
    const float* sW3, const float* sB3, float* __restrict__ energy)
{
    const float* w1  = w1base  + e * P_ * H_;
    const float* w1t = w1tbase + e * P_ * H_;
    const float* w2  = w2base  + e * H_ * H_;
    const float* w2t = w2tbase + e * H_ * H_;
    const float* w3  = sW3 + e * H_;

    float h1[H_];
    #pragma unroll
    for (int h = 0; h < H_; h++) h1[h] = sB1[e * H_ + h];

    const float4* xrow = (const float4*)(fps + (size_t)a * P_);
    #pragma unroll 2
    for (int p4 = 0; p4 < P_ / 4; p4++) {
        float4 x = xrow[p4];
        #pragma unroll
        for (int h = 0; h < H_; h++) {
            float4 w = *(const float4*)(w1t + h * P_ + p4 * 4);
            float s = fmaf(x.x, w.x, h1[h]);
            s = fmaf(x.y, w.y, s);
            s = fmaf(x.z, w.z, s);
            h1[h] = fmaf(x.w, w.w, s);
        }
    }
    #pragma unroll
    for (int h = 0; h < H_; h++) h1[h] = tanh_fast(h1[h]);

    float g2[H_];
    #pragma unroll
    for (int j = 0; j < H_; j++) {
        float s = sB2[e * H_ + j];
        #pragma unroll
        for (int h4 = 0; h4 < H_ / 4; h4++) {
            float4 w = *(const float4*)(w2t + j * H_ + h4 * 4);
            s = fmaf(h1[h4 * 4],     w.x, s);
            s = fmaf(h1[h4 * 4 + 1], w.y, s);
            s = fmaf(h1[h4 * 4 + 2], w.z, s);
            s = fmaf(h1[h4 * 4 + 3], w.w, s);
        }
        g2[j] = tanh_fast(s);
    }

    float en = sB3[e];
    #pragma unroll
    for (int j = 0; j < H_; j++) {
        float v = g2[j];
        en = fmaf(v, w3[j], en);
        g2[j] = w3[j] * (1.0f - v * v);
    }
    atomicAdd(&energy[key], en);

    #pragma unroll
    for (int h = 0; h < H_; h++) {
        float s = 0.0f;
        #pragma unroll
        for (int j4 = 0; j4 < H_ / 4; j4++) {
            float4 w = *(const float4*)(w2 + h * H_ + j4 * 4);
            s = fmaf(w.x, g2[j4 * 4],     s);
            s = fmaf(w.y, g2[j4 * 4 + 1], s);
            s = fmaf(w.z, g2[j4 * 4 + 2], s);
            s = fmaf(w.w, g2[j4 * 4 + 3], s);
        }
        h1[h] = s * (1.0f - h1[h] * h1[h]);
    }

    float4* dst = (float4*)(g_dE + (size_t)pos * P_);
    #pragma unroll 2
    for (int p4 = 0; p4 < P_ / 4; p4++) {
        float4 o;
        #pragma unroll
        for (int pp = 0; pp < 4; pp++) {
            const float* w1p = w1 + (p4 * 4 + pp) * H_;
            float s = 0.0f;
            #pragma unroll
            for (int h4 = 0; h4 < H_ / 4; h4++) {
                float4 w = *(const float4*)(w1p + h4 * 4);
                s = fmaf(w.x, h1[h4 * 4],     s);
                s = fmaf(w.y, h1[h4 * 4 + 1], s);
                s = fmaf(w.z, h1[h4 * 4 + 2], s);
                s = fmaf(w.w, h1[h4 * 4 + 3], s);
            }
            ((float*)&o)[pp] = -s;
        }
        dst[p4] = o;
    }
}

// ---------------------------------------------------------------------------
// Fused: stable rank + dual-atom MLP. Each thread handles 2 atoms (sub-block
// 0 and 1 of a 512-atom CTA) so every broadcast weight LDS.128 feeds 8 FMAs
// instead of 4. Warp-uniform fast path requires e0==e1 and both atoms valid;
// the rare boundary warps (~2/352 CTAs) fall back to two single-atom passes.
// ---------------------------------------------------------------------------
__global__ void __launch_bounds__(AB, 2) k_mlp(
    const float* __restrict__ fps, const float* __restrict__ W1,
    const float* __restrict__ b1,  const float* __restrict__ W2,
    const float* __restrict__ b2,  const float* __restrict__ W3,
    const float* __restrict__ b3,  const int* __restrict__ idx,
    float* __restrict__ energy)
{
    __shared__ __align__(16) float sW1 [E_ * P_ * H_];   // [P][H]
    __shared__ __align__(16) float sW1T[E_ * P_ * H_];   // [H][P]
    __shared__ __align__(16) float sW2 [E_ * H_ * H_];   // [h][j]
    __shared__ __align__(16) float sW2T[E_ * H_ * H_];   // [j][h]
    __shared__ float sB1[E_ * H_];
    __shared__ float sB2[E_ * H_];
    __shared__ float sW3[E_ * H_];
    __shared__ float sB3[E_];
    __shared__ int   skey[2 * AB];

    int t = threadIdx.x;
    for (int i = t; i < E_ * P_ * H_; i += AB) {
        float v = W1[i];
        sW1[i] = v;
        int e = i / (P_ * H_), r = i % (P_ * H_);
        int p = r / H_, h = r % H_;
        sW1T[e * P_ * H_ + h * P_ + p] = v;
    }
    for (int i = t; i < E_ * H_ * H_; i += AB) {
        float v = W2[i];
        sW2[i] = v;
        int e = i / (H_ * H_), r = i % (H_ * H_);
        int hh = r / H_, j = r % H_;
        sW2T[e * H_ * H_ + j * H_ + hh] = v;
    }
    for (int i = t; i < E_ * H_; i += AB) {
        sB1[i] = b1[i];
        sB2[i] = b2[i];
        sW3[i] = W3[i];
    }
    if (t < E_) sB3[t] = b3[t];

    int blk0 = blockIdx.x * 2;           // hist block ids blk0, blk0+1
    int a0 = blockIdx.x * (2 * AB) + t;  // always < Q_ (max 179967)
    int a1 = a0 + AB;
    bool ok1 = (a1 < Q_);
    int key0 = idx[a0];
    int key1 = ok1 ? idx[a1] : -1;
    skey[t] = key0;
    skey[AB + t] = key1;
    __syncthreads();

    // stable local ranks within each 256-atom sub-block (broadcast LDS)
    int lr0 = 0, lr1 = 0;
    {
        int j = 0;
        #pragma unroll 4
        for (; j + 4 <= t; j += 4) {
            lr0 += (skey[j]     == key0) + (skey[j + 1] == key0)
                 + (skey[j + 2] == key0) + (skey[j + 3] == key0);
            lr1 += (skey[AB + j]     == key1) + (skey[AB + j + 1] == key1)
                 + (skey[AB + j + 2] == key1) + (skey[AB + j + 3] == key1);
        }
        for (; j < t; j++) {
            lr0 += (skey[j] == key0);
            lr1 += (skey[AB + j] == key1);
        }
    }
    int pos0 = g_key_base[key0] + g_hist[(size_t)key0 * NB + blk0] + lr0;
    int pos1 = ok1 ? (g_key_base[key1] + g_hist[(size_t)key1 * NB + blk0 + 1] + lr1) : 0;

    int e0 = a0 / QE_;
    int e1 = a1 / QE_;
    bool fast = __all_sync(0xFFFFFFFFu, ok1 && (e0 == e1));

    if (!fast) {
        mlp_one(fps, a0, e0, pos0, key0, sW1, sW1T, sW2, sW2T, sB1, sB2, sW3, sB3, energy);
        if (ok1)
            mlp_one(fps, a1, e1, pos1, key1, sW1, sW1T, sW2, sW2T, sB1, sB2, sW3, sB3, energy);
        return;
    }

    // ---------------- dual-atom fast path (e0 == e1 == e) ----------------
    int e = e0;
    const float* w1  = sW1  + e * P_ * H_;
    const float* w1t = sW1T + e * P_ * H_;
    const float* w2  = sW2  + e * H_ * H_;
    const float* w2t = sW2T + e * H_ * H_;
    const float* w3  = sW3 + e * H_;

    float h1a[H_], h1b[H_];
    #pragma unroll
    for (int h = 0; h < H_; h++) { h1a[h] = sB1[e * H_ + h]; h1b[h] = h1a[h]; }

    const float4* x0 = (const float4*)(fps + (size_t)a0 * P_);
    const float4* x1 = (const float4*)(fps + (size_t)a1 * P_);
    #pragma unroll 2
    for (int p4 = 0; p4 < P_ / 4; p4++) {
        float4 xa = x0[p4];
        float4 xb = x1[p4];
        #pragma unroll
        for (int h = 0; h < H_; h++) {
            float4 w = *(const float4*)(w1t + h * P_ + p4 * 4);
            float sa = fmaf(xa.x, w.x, h1a[h]);
            float sb = fmaf(xb.x, w.x, h1b[h]);
            sa = fmaf(xa.y, w.y, sa);  sb = fmaf(xb.y, w.y, sb);
            sa = fmaf(xa.z, w.z, sa);  sb = fmaf(xb.z, w.z, sb);
            h1a[h] = fmaf(xa.w, w.w, sa);
            h1b[h] = fmaf(xb.w, w.w, sb);
        }
    }
    #pragma unroll
    for (int h = 0; h < H_; h++) { h1a[h] = tanh_fast(h1a[h]); h1b[h] = tanh_fast(h1b[h]); }

    float g2a[H_], g2b[H_];
    #pragma unroll
    for (int j = 0; j < H_; j++) {
        float sa = sB2[e * H_ + j];
        float sb = sa;
        #pragma unroll
        for (int h4 = 0; h4 < H_ / 4; h4++) {
            float4 w = *(const float4*)(w2t + j * H_ + h4 * 4);
            sa = fmaf(h1a[h4 * 4],     w.x, sa);  sb = fmaf(h1b[h4 * 4],     w.x, sb);
            sa = fmaf(h1a[h4 * 4 + 1], w.y, sa);  sb = fmaf(h1b[h4 * 4 + 1], w.y, sb);
            sa = fmaf(h1a[h4 * 4 + 2], w.z, sa);  sb = fmaf(h1b[h4 * 4 + 2], w.z, sb);
            sa = fmaf(h1a[h4 * 4 + 3], w.w, sa);  sb = fmaf(h1b[h4 * 4 + 3], w.w, sb);
        }
        g2a[j] = tanh_fast(sa);
        g2b[j] = tanh_fast(sb);
    }

    float ena = sB3[e], enb = ena;
    #pragma unroll
    for (int j = 0; j < H_; j++) {
        float w3j = w3[j];
        float va = g2a[j], vb = g2b[j];
        ena = fmaf(va, w3j, ena);
        enb = fmaf(vb, w3j, enb);
        g2a[j] = w3j * (1.0f - va * va);
        g2b[j] = w3j * (1.0f - vb * vb);
    }
    atomicAdd(&energy[key0], ena);
    atomicAdd(&energy[key1], enb);

    // g1 overwrites h1 in place
    #pragma unroll
    for (int h = 0; h < H_; h++) {
        float sa = 0.0f, sb = 0.0f;
        #pragma unroll
        for (int j4 = 0; j4 < H_ / 4; j4++) {
            float4 w = *(const float4*)(w2 + h * H_ + j4 * 4);
            sa = fmaf(w.x, g2a[j4 * 4],     sa);  sb = fmaf(w.x, g2b[j4 * 4],     sb);
            sa = fmaf(w.y, g2a[j4 * 4 + 1], sa);  sb = fmaf(w.y, g2b[j4 * 4 + 1], sb);
            sa = fmaf(w.z, g2a[j4 * 4 + 2], sa);  sb = fmaf(w.z, g2b[j4 * 4 + 2], sb);
            sa = fmaf(w.w, g2a[j4 * 4 + 3], sa);  sb = fmaf(w.w, g2b[j4 * 4 + 3], sb);
        }
        h1a[h] = sa * (1.0f - h1a[h] * h1a[h]);
        h1b[h] = sb * (1.0f - h1b[h] * h1b[h]);
    }

    float4* dst0 = (float4*)(g_dE + (size_t)pos0 * P_);
    float4* dst1 = (float4*)(g_dE + (size_t)pos1 * P_);
    #pragma unroll 2
    for (int p4 = 0; p4 < P_ / 4; p4++) {
        float4 oa, ob;
        #pragma unroll
        for (int pp = 0; pp < 4; pp++) {
            const float* w1p = w1 + (p4 * 4 + pp) * H_;
            float sa = 0.0f, sb = 0.0f;
            #pragma unroll
            for (int h4 = 0; h4 < H_ / 4; h4++) {
                float4 w = *(const float4*)(w1p + h4 * 4);
                sa = fmaf(w.x, h1a[h4 * 4],     sa);  sb = fmaf(w.x, h1b[h4 * 4],     sb);
                sa = fmaf(w.y, h1a[h4 * 4 + 1], sa);  sb = fmaf(w.y, h1b[h4 * 4 + 1], sb);
                sa = fmaf(w.z, h1a[h4 * 4 + 2], sa);  sb = fmaf(w.z, h1b[h4 * 4 + 2], sb);
                sa = fmaf(w.w, h1a[h4 * 4 + 3], sa);  sb = fmaf(w.w, h1b[h4 * 4 + 3], sb);
            }
            ((float*)&oa)[pp] = -sa;
            ((float*)&ob)[pp] = -sb;
        }
        dst0[p4] = oa;
        dst1[p4] = ob;
    }
}

// ---------------------------------------------------------------------------
// Sparse COO transpose-matvec (best-known form): one int4-group/thread,
// __ldcs streaming on COO arrays so g_dE + force stay L2-resident.
// ---------------------------------------------------------------------------
__global__ void k_scatter(const int4* __restrict__ rows,
                          const int4* __restrict__ cols,
                          const float4* __restrict__ vals,
                          float* __restrict__ force)
{
    int i = blockIdx.x * blockDim.x + threadIdx.x;
    if (i >= NNZ_ / 4) return;
    int4   r = __ldcs(&rows[i]);
    int4   c = __ldcs(&cols[i]);
    float4 v = __ldcs(&vals[i]);
    float d0 = __ldg(&g_dE[r.x]);
    float d1 = __ldg(&g_dE[r.y]);
    float d2 = __ldg(&g_dE[r.z]);
    float d3 = __ldg(&g_dE[r.w]);
    atomicAdd(&force[c.x], v.x * d0);
    atomicAdd(&force[c.y], v.y * d1);
    atomicAdd(&force[c.z], v.z * d2);
    atomicAdd(&force[c.w], v.w * d3);
}

// ---------------------------------------------------------------------------
extern "C" void kernel_launch(void* const* d_in, const int* in_sizes, int n_in,
                              void* d_out, int out_size)
{
    const float* fps       = (const float*)d_in[0];
    const float* W1        = (const float*)d_in[1];
    const float* b1        = (const float*)d_in[2];
    const float* W2        = (const float*)d_in[3];
    const float* b2        = (const float*)d_in[4];
    const float* W3        = (const float*)d_in[5];
    const float* b3        = (const float*)d_in[6];
    const int*   image_idx = (const int*)d_in[7];
    const int*   fp_rows   = (const int*)d_in[8];
    const int*   fp_cols   = (const int*)d_in[9];
    const float* fp_vals   = (const float*)d_in[10];

    float* out    = (float*)d_out;
    float* energy = out;               // [NIMG, 1]
    float* force  = out + NIMG_;       // [Q, 3] flattened

    k_hist<<<NB, AB>>>(image_idx, out, out_size);
    k_scan_blocks<<<NIMG_, NB>>>();
    k_scan_keys<<<1, 1024>>>();

    k_mlp<<<NBD, AB>>>(fps, W1, b1, W2, b2, W3, b3, image_idx, energy);

    k_scatter<<<(NNZ_ / 4 + 255) / 256, 256>>>(
        (const int4*)fp_rows, (const int4*)fp_cols, (const float4*)fp_vals, force);
}